// round 15
// baseline (speedup 1.0000x reference)
#include <cuda_runtime.h>
#include <cuda_bf16.h>
#include <stdint.h>

#define B 32
#define H 512
#define W 512
#define HW (H*W)            // 262144
#define WW 16               // words per row (512/32)

__device__ unsigned g_weak[B*H*WW];     // 1 MB
__device__ unsigned g_strong[B*H*WW];   // 1 MB

// ---- exact gray math ----
__device__ __forceinline__ float u8f(float v) {
    float t = __fmaf_rn(v, 128.0f, 128.0f);   // == rn(rn(v+1)*128); >=0 since v>=-1
    return floorf(fminf(t, 255.0f));
}

__device__ __forceinline__ int grayf(float r, float g, float b) {
    float t = __fadd_rn(__fadd_rn(__fmul_rn(0.299f, u8f(r)),
                                  __fmul_rn(0.587f, u8f(g))),
                        __fmul_rn(0.114f, u8f(b)));
    return __float2int_rn(t);   // round half to even == jnp.round
}

// angle-bin constants at 2^30 scale (decision-exact, see R9)
#define T1_30 444758425ULL
#define T2_30 2592242073ULL

// ------------- Fused Kernel 1: RGB -> gray -> Sobel -> NMS -> bitmasks -------------
// Tile 128x8 core, block (128,2)=256 threads, 4 blocks/SM: four INDEPENDENT
// barrier schedules per SM so one block's fill-phase DRAM tail hides behind
// the compute phases of the other three (phase decorrelation).
__global__ void __launch_bounds__(256, 4) k_gsobel(const float* __restrict__ x) {
    __shared__ int G[12][136];   // gray, rows tileY-2..+9, cols tileX-4..+131 (6.4KB)
    __shared__ int M[10][132];   // mag,  rows tileY-1..+8, cols tileX-1..+130 (5.3KB)

    int b = blockIdx.z;
    int tileX = blockIdx.x * 128, tileY = blockIdx.y * 8;
    int tx = threadIdx.x, ty = threadIdx.y;
    int tid = ty * 128 + tx;
    const float* xr = x + (size_t)b * 3 * HW;

    // ---- gray fill: 12 rows x 34 aligned 4-pixel groups (408 groups / 256 thr) ----
    for (int i = tid; i < 12 * 34; i += 256) {
        int r = i / 34, j = i - r * 34;
        int gy = min(max(tileY - 2 + r, 0), H - 1);
        int gx0 = tileX - 4 + 4 * j;
        int4 o;
        if (gx0 >= 0 && gx0 <= W - 4) {          // aligned fast path
            const float4* pr = (const float4*)(xr + (size_t)gy * W) + (gx0 >> 2);
            float4 rr = pr[0];
            float4 gg = pr[HW / 4];
            float4 bb = pr[2 * (HW / 4)];
            o.x = grayf(rr.x, gg.x, bb.x);
            o.y = grayf(rr.y, gg.y, bb.y);
            o.z = grayf(rr.z, gg.z, bb.z);
            o.w = grayf(rr.w, gg.w, bb.w);
        } else {                                  // border clamp (x-edge tiles only)
            int v[4];
#pragma unroll
            for (int e = 0; e < 4; e++) {
                int gx = min(max(gx0 + e, 0), W - 1);
                int p = gy * W + gx;
                v[e] = grayf(xr[p], xr[HW + p], xr[2 * HW + p]);
            }
            o.x = v[0]; o.y = v[1]; o.z = v[2]; o.w = v[3];
        }
        *(int4*)&G[r][4 * j] = o;
    }
    __syncthreads();

    // ---- Sobel for own 4 core pixels (rows ty*4..ty*4+3), separable ----
    int gxr[4], gyr[4], mreg[4];
    {
        int cl = tx + 3, cc = tx + 4, cr = tx + 5;   // G cols: px-1, px, px+1
        int rb = ty * 4 + 1;                         // G row of (core row ly) - 1
        int L[6], C[6], R[6], hs[6];
#pragma unroll
        for (int q = 0; q < 6; q++) {
            L[q] = G[rb + q][cl];
            C[q] = G[rb + q][cc];
            R[q] = G[rb + q][cr];
            hs[q] = (L[q] + R[q]) + 2 * C[q];        // shared: hs2_k == hs0_{k+2}
        }
#pragma unroll
        for (int k = 0; k < 4; k++) {
            int vr = R[k] + 2 * R[k + 1] + R[k + 2];
            int vl = L[k] + 2 * L[k + 1] + L[k + 2];
            gxr[k] = vr - vl;
            gyr[k] = hs[k + 2] - hs[k];
            mreg[k] = abs(gxr[k]) + abs(gyr[k]);
            M[ty * 4 + k + 1][tx + 1] = mreg[k];
        }
    }

    // ---- halo mag ring: 276 pixels (rows -1,8 width 130; cols -1,128 rows 0..7) ----
    for (int i = tid; i < 276; i += 256) {
        int ly, lx;
        if (i < 130)      { ly = -1;       lx = i - 1; }
        else if (i < 260) { ly = 8;        lx = i - 131; }
        else if (i < 268) { ly = i - 260;  lx = -1; }
        else              { ly = i - 268;  lx = 128; }
        int py = tileY + ly, px = tileX + lx;
        int m = 0;
        if (py >= 0 && py < H && px >= 0 && px < W) {   // mag zero-padded outside
            int r0 = ly + 2, c0 = lx + 4;
            int gxv = (G[r0-1][c0+1] + 2*G[r0][c0+1] + G[r0+1][c0+1])
                    - (G[r0-1][c0-1] + 2*G[r0][c0-1] + G[r0+1][c0-1]);
            int gyv = (G[r0+1][c0-1] + 2*G[r0+1][c0] + G[r0+1][c0+1])
                    - (G[r0-1][c0-1] + 2*G[r0-1][c0] + G[r0-1][c0+1]);
            m = abs(gxv) + abs(gyv);
        }
        M[ly + 1][lx + 1] = m;
    }
    __syncthreads();

    // ---- NMS + thresholds: branchless bin select via flat offset ----
    const int* Mf = &M[0][0];
#pragma unroll
    for (int k = 0; k < 4; k++) {
        int ly = ty * 4 + k;
        int py = tileY + ly, px = tileX + tx;
        int gxv = gxr[k], gyv = gyr[k], m = mreg[k];
        int base = (ly + 1) * 132 + (tx + 1);

        unsigned ax = (unsigned)abs(gxv);
        unsigned ay = (unsigned)abs(gyv);
        unsigned long long ay30 = ((unsigned long long)ay) << 30;
        bool p0 = ay30 < T1_30 * ax;               // ~horizontal gradient
        bool p2 = ay30 > T2_30 * ax;               // ~vertical
        bool pd = ((gxv ^ gyv) >= 0);              // same sign (only used when !p0 && !p2)
        int off = p0 ? 1 : (p2 ? 132 : (pd ? 133 : -131));
        int q1 = Mf[base + off];
        int q2 = Mf[base - off];

        bool keep   = (m >= q1) && (m >= q2);
        bool weak   = keep && (m > 40);
        bool strong = keep && (m > 85);

        unsigned wmask = __ballot_sync(0xffffffffu, weak);
        unsigned smask = __ballot_sync(0xffffffffu, strong);
        if ((tx & 31) == 0) {
            int wi = b * (H * WW) + py * WW + (px >> 5);
            g_weak[wi]   = wmask;
            g_strong[wi] = smask;
        }
    }
}

// ------------- Kernel 2: hysteresis, 64-bit column pairs (unchanged, ~10.7us) -------------
#define RPT64 3
#define NSLOT (128*RPT64)    // 384

__global__ void __launch_bounds__(1024, 1) k_hyst(float* __restrict__ out) {
    __shared__ union {
        struct {
            unsigned long long Bt[2][128][8];
            unsigned long long Bb[2][128][8];
        } x;
        unsigned SS[NSLOT * 16];
    } sm;

    int blk = blockIdx.x;
    int b = blk >> 2, s = blk & 3;
    int ybase = max(0, 128 * s - 100);
    int yend  = min(512, 128 * s + 228);
    int nrows = yend - ybase;
    int coreBase = 128 * s - ybase;

    int tid = threadIdx.x;
    int xp = tid & 7;
    int yg = tid >> 3;
    int slot0 = yg * RPT64;

    int wslot0 = (tid >> 5) * 12;
    int mind = max(0, max(coreBase - (wslot0 + 11), wslot0 - (coreBase + 127)));
    int tmax = 100 - mind;

    const unsigned long long* wb = (const unsigned long long*)(g_weak   + b * (H * WW));
    const unsigned long long* sb = (const unsigned long long*)(g_strong + b * (H * WW));

    unsigned long long wk[RPT64], st[RPT64];
#pragma unroll
    for (int i = 0; i < RPT64; i++) {
        int slot = slot0 + i;
        if (slot < nrows) {
            int gy = ybase + slot;
            wk[i] = wb[gy * 8 + xp];
            st[i] = sb[gy * 8 + xp];
        } else { wk[i] = 0ull; st[i] = 0ull; }
    }
    unsigned lmask = (xp == 0) ? 0u : 0xffffffffu;
    unsigned rmask = (xp == 7) ? 0u : 0xffffffffu;

    unsigned d = 1u;
    for (int t = 0; t < 100; ++t) {
        int tb = t & 1;
        bool act = (t <= tmax);
        unsigned long long h[RPT64];
        if (act) {
#pragma unroll
            for (int i = 0; i < RPT64; i++) {
                unsigned long long c = st[i];
                unsigned hi = (unsigned)(c >> 32), lo = (unsigned)c;
                unsigned lh = __shfl_up_sync(0xffffffffu, hi, 1) & lmask;
                unsigned rl = __shfl_down_sync(0xffffffffu, lo, 1) & rmask;
                h[i] = c | (c << 1) | (c >> 1)
                     | (unsigned long long)(lh >> 31)
                     | ((unsigned long long)(rl & 1u) << 63);
            }
            sm.x.Bt[tb][yg][xp] = h[0];
            sm.x.Bb[tb][yg][xp] = h[RPT64 - 1];
        }

        int conv = __syncthreads_or((int)d);
        if (!conv) break;

        if (act) {
            unsigned long long hup = (yg > 0)   ? sm.x.Bb[tb][yg - 1][xp] : 0ull;
            unsigned long long hdn = (yg < 127) ? sm.x.Bt[tb][yg + 1][xp] : 0ull;

            unsigned long long d64 = 0ull, ns;
            ns = wk[0] & (hup | h[0] | h[1]);  d64 |= ns ^ st[0]; st[0] = ns;
            ns = wk[1] & (h[0] | h[1] | h[2]); d64 |= ns ^ st[1]; st[1] = ns;
            ns = wk[2] & (h[1] | h[2] | hdn);  d64 |= ns ^ st[2]; st[2] = ns;
            d = (d64 != 0ull) ? 1u : 0u;
        } else {
            d = 0u;
        }
    }
    __syncthreads();

#pragma unroll
    for (int i = 0; i < RPT64; i++) {
        sm.SS[(slot0 + i) * 16 + 2 * xp]     = (unsigned)st[i];
        sm.SS[(slot0 + i) * 16 + 2 * xp + 1] = (unsigned)(st[i] >> 32);
    }
    __syncthreads();

    float* ob = out + (size_t)b * HW + (size_t)(128 * s) * W;
    for (int p4 = tid; p4 < 128 * 128; p4 += 1024) {
        int y = p4 >> 7;
        int x4 = p4 & 127;
        unsigned w = sm.SS[(coreBase + y) * 16 + (x4 >> 3)];
        int sh = (x4 & 7) * 4;
        float4 o;
        o.x = ((w >> (sh + 0)) & 1u) ? 255.0f : 0.0f;
        o.y = ((w >> (sh + 1)) & 1u) ? 255.0f : 0.0f;
        o.z = ((w >> (sh + 2)) & 1u) ? 255.0f : 0.0f;
        o.w = ((w >> (sh + 3)) & 1u) ? 255.0f : 0.0f;
        ((float4*)(ob + y * W))[x4] = o;
    }
}

extern "C" void kernel_launch(void* const* d_in, const int* in_sizes, int n_in,
                              void* d_out, int out_size) {
    const float* x = (const float*)d_in[0];
    float* out = (float*)d_out;

    k_gsobel<<<dim3(W/128, H/8, B), dim3(128, 2)>>>(x);
    k_hyst<<<B * 4, 1024>>>(out);
}